// round 13
// baseline (speedup 1.0000x reference)
#include <cuda_runtime.h>
#include <cuda_fp16.h>
#include <mma.h>
#include <cstddef>

#define N_NODES 100000
#define N_EDGES 1600000
#define IN_C  128
#define HID_C 128
#define OUT_C 64

#define SCAN_B 512
#define N_SCAN_BLKS ((N_NODES + SCAN_B - 1) / SCAN_B)   // 196
#define CHUNK0 50048                                     // 391 * 128, gemm tile aligned

// ---------------- scratch (module-static; no allocations) ----------------
__device__ int    g_cnt   [N_NODES];
__device__ int    g_row   [N_NODES + 1];
__device__ int    g_cursor[N_NODES];
__device__ int    g_bsum  [N_SCAN_BLKS];
__device__ int    g_srcs  [N_EDGES];                     // src ids sorted by dst
__device__ float  g_dinv  [N_NODES];
__device__ __half g_w1t   [(size_t)HID_C * IN_C];        // W1^T fp16: [n][k]
__device__ __half g_w2t   [(size_t)OUT_C * HID_C];       // W2^T fp16: [n][k]
__device__ __half g_h1s   [(size_t)N_NODES * HID_C];     // fp16: (x @ W1)[n]  (UNscaled)
__device__ __half g_agg1r [(size_t)N_NODES * HID_C];     // fp16: dinv[n]*relu(layer1[n])
__device__ __half g_h2s   [(size_t)N_NODES * OUT_C];     // fp16: dinv[n]*(relu1[n] @ W2)

// ---------------- GEMM-branch init: weight transpose/convert ----------------
__global__ void k_prep_w(const float* __restrict__ W1, const float* __restrict__ W2) {
    int i = blockIdx.x * blockDim.x + threadIdx.x;
    int stride = gridDim.x * blockDim.x;
    for (int j = i; j < HID_C * IN_C; j += stride) {     // Wt1[n][k] = W1[k][n]
        int n = j / IN_C, k = j % IN_C;
        g_w1t[j] = __float2half_rn(W1[(size_t)k * HID_C + n]);
    }
    for (int j = i; j < OUT_C * HID_C; j += stride) {    // Wt2[n][k] = W2[k][n]
        int n = j / HID_C, k = j % HID_C;
        g_w2t[j] = __float2half_rn(W2[(size_t)k * OUT_C + n]);
    }
}

// 4 edges per thread (int4 loads); N_EDGES % 4 == 0
__global__ void k_hist(const int* __restrict__ dst) {
    int i = blockIdx.x * blockDim.x + threadIdx.x;
    if (i < N_EDGES / 4) {
        int4 d = __ldg(&((const int4*)dst)[i]);
        atomicAdd(&g_cnt[d.x], 1);
        atomicAdd(&g_cnt[d.y], 1);
        atomicAdd(&g_cnt[d.z], 1);
        atomicAdd(&g_cnt[d.w], 1);
    }
}

// per-block inclusive scan of 512 counts; also computes dinv = rsqrt(cnt+1)
__global__ void k_scan1() {
    __shared__ int sh[SCAN_B];
    int i = blockIdx.x * SCAN_B + threadIdx.x;
    int v = (i < N_NODES) ? g_cnt[i] : 0;
    if (i < N_NODES) g_dinv[i] = rsqrtf((float)(v + 1));   // +1 self loop
    sh[threadIdx.x] = v;
    __syncthreads();
#pragma unroll
    for (int off = 1; off < SCAN_B; off <<= 1) {
        int t = (threadIdx.x >= off) ? sh[threadIdx.x - off] : 0;
        __syncthreads();
        sh[threadIdx.x] += t;
        __syncthreads();
    }
    if (i < N_NODES) g_row[i] = sh[threadIdx.x] - v;       // exclusive within block
    if (threadIdx.x == SCAN_B - 1) g_bsum[blockIdx.x] = sh[SCAN_B - 1];
}

// each block redundantly scans the 196 block sums, then applies offsets
__global__ void k_scan3() {
    __shared__ int bo[256];
    int t = threadIdx.x;
    int v = (t < N_SCAN_BLKS) ? g_bsum[t] : 0;
    bo[t] = v;
    __syncthreads();
#pragma unroll
    for (int off = 1; off < 256; off <<= 1) {
        int u = (t >= off) ? bo[t - off] : 0;
        __syncthreads();
        bo[t] += u;
        __syncthreads();
    }
    // exclusive offset for block b = bo[b] - bsum[b]
    int i = blockIdx.x * blockDim.x + t;
    if (i < N_NODES) {
        int r = g_row[i] + bo[i >> 9] - g_bsum[i >> 9];
        g_row[i] = r;
        g_cursor[i] = r;
    }
    if (blockIdx.x == 0 && t == 0) g_row[N_NODES] = N_EDGES;
}

// 4 edges per thread (int4 loads)
__global__ void k_fill(const int* __restrict__ src, const int* __restrict__ dst) {
    int i = blockIdx.x * blockDim.x + threadIdx.x;
    if (i < N_EDGES / 4) {
        int4 d = __ldg(&((const int4*)dst)[i]);
        int4 s = __ldg(&((const int4*)src)[i]);
        g_srcs[atomicAdd(&g_cursor[d.x], 1)] = s.x;
        g_srcs[atomicAdd(&g_cursor[d.y], 1)] = s.y;
        g_srcs[atomicAdd(&g_cursor[d.z], 1)] = s.z;
        g_srcs[atomicAdd(&g_cursor[d.w], 1)] = s.w;
    }
}

// ---------------- tensor-core GEMM: C[M,NC] = half( A[M,128] @ Wt^T ) ----------------
// A (fp32 or fp16) row-major stride 128, Wt fp16 [NC][128], C fp16 row-major stride NC.
// Processes rows [rowbase + blockIdx*128, ...), bounded by M.
template<int NC, typename TA>
__global__ void __launch_bounds__(256) k_gemm_mma(const TA* __restrict__ A,
                                                  const __half* __restrict__ Wt,
                                                  __half* __restrict__ C, int M, int rowbase) {
    using namespace nvcuda;
    constexpr int KC = 64, ST = KC + 16;   // smem stride (halves), 32B-aligned rows
    constexpr int NFR = NC / 32;           // n-frags per warp: 128->4, 64->2

    __shared__ __half As[128 * ST];
    __shared__ __half Bs[NC * ST];

    const int tid    = threadIdx.x;
    const int wid    = tid >> 5;
    const int lane   = tid & 31;
    const int warp_m = wid & 3;            // 4 warp-rows x 32 rows
    const int warp_n = wid >> 2;           // 2 warp-cols x NC/2 cols
    const int row_blk = rowbase + blockIdx.x * 128;

    wmma::fragment<wmma::accumulator, 16, 16, 16, float> cf[2][NFR];
#pragma unroll
    for (int i = 0; i < 2; i++)
#pragma unroll
        for (int j = 0; j < NFR; j++) wmma::fill_fragment(cf[i][j], 0.f);

    for (int kc = 0; kc < 128; kc += KC) {
        // A chunk: 128 rows x 64 elems as fp16. 2 thr/row (32 elems each).
        {
            int r = tid >> 1;
            int hh = tid & 1;
            int grow = row_blk + r;
            __half* sp = As + r * ST + hh * 32;
            if (sizeof(TA) == 4) {         // fp32 input: convert
                const float4* gp = (const float4*)((const float*)A + (size_t)grow * 128 + kc + hh * 32);
#pragma unroll
                for (int j = 0; j < 8; j++) {
                    float4 v = (grow < M) ? __ldg(&gp[j]) : make_float4(0.f, 0.f, 0.f, 0.f);
                    ((__half2*)(sp + j * 4))[0] = __floats2half2_rn(v.x, v.y);
                    ((__half2*)(sp + j * 4))[1] = __floats2half2_rn(v.z, v.w);
                }
            } else {                       // fp16 input: pure uint4 copy
                const uint4* gp = (const uint4*)((const __half*)A + (size_t)grow * 128 + kc + hh * 32);
#pragma unroll
                for (int j = 0; j < 4; j++) {
                    uint4 v = (grow < M) ? __ldg(&gp[j]) : make_uint4(0, 0, 0, 0);
                    *(uint4*)(sp + j * 8) = v;
                }
            }
        }
        // B chunk: NC rows x 64 halves (uint4 copies)
        {
#pragma unroll
            for (int i = 0; i < (NC * 8) / 256; i++) {
                int u = tid + i * 256;
                int n = u >> 3, k8 = u & 7;
                uint4 v = *(const uint4*)(Wt + (size_t)n * 128 + kc + k8 * 8);
                *(uint4*)(Bs + n * ST + k8 * 8) = v;
            }
        }
        __syncthreads();

#pragma unroll
        for (int kf = 0; kf < KC / 16; kf++) {
            wmma::fragment<wmma::matrix_a, 16, 16, 16, __half, wmma::row_major> af[2];
            wmma::load_matrix_sync(af[0], As + (warp_m * 32 +  0) * ST + kf * 16, ST);
            wmma::load_matrix_sync(af[1], As + (warp_m * 32 + 16) * ST + kf * 16, ST);
#pragma unroll
            for (int nf = 0; nf < NFR; nf++) {
                wmma::fragment<wmma::matrix_b, 16, 16, 16, __half, wmma::col_major> bf;
                wmma::load_matrix_sync(bf, Bs + (warp_n * (NC / 2) + nf * 16) * ST + kf * 16, ST);
                wmma::mma_sync(cf[0][nf], af[0], bf, cf[0][nf]);
                wmma::mma_sync(cf[1][nf], af[1], bf, cf[1][nf]);
            }
        }
        __syncthreads();   // protects As/Bs before next chunk / staging reuse
    }

    // epilogue: stage fp32 frag -> convert fp16 -> gmem (per-warp disjoint staging in As)
    float* stage = (float*)As + wid * 256;
#pragma unroll
    for (int mf = 0; mf < 2; mf++) {
        int row0 = row_blk + warp_m * 32 + mf * 16;
        if (row0 + 16 > M) continue;          // M is a multiple of 16
#pragma unroll
        for (int nf = 0; nf < NFR; nf++) {
            wmma::store_matrix_sync(stage, cf[mf][nf], 16, wmma::mem_row_major);
            __syncwarp();
            int r = lane >> 1, c = (lane & 1) * 8;
            const float* sp = stage + r * 16 + c;
            __half hv[8];
#pragma unroll
            for (int j = 0; j < 8; j++) hv[j] = __float2half_rn(sp[j]);
            int col0 = warp_n * (NC / 2) + nf * 16 + c;
            *(uint4*)(C + (size_t)(row0 + r) * NC + col0) = *(uint4*)hv;
            __syncwarp();
        }
    }
}

// accumulate 8 fp16 channels (one uint4) scaled by s into fp32 accumulator
__device__ __forceinline__ void acc8s(float* a, uint4 u, float s) {
    const __half2* h = (const __half2*)&u;
#pragma unroll
    for (int i = 0; i < 4; i++) {
        float2 f = __half22float2(h[i]);
        a[2 * i]     = fmaf(f.x, s, a[2 * i]);
        a[2 * i + 1] = fmaf(f.y, s, a[2 * i + 1]);
    }
}

// accumulate 8 fp16 channels (one uint4) into fp32 accumulator
__device__ __forceinline__ void acc8(float* a, uint4 u) {
    const __half2* h = (const __half2*)&u;
#pragma unroll
    for (int i = 0; i < 4; i++) {
        float2 f = __half22float2(h[i]);
        a[2 * i]     += f.x;
        a[2 * i + 1] += f.y;
    }
}

// ---------------- layer-1 pull aggregation: 16 lanes per dst node (8 ch each) ----------------
// Processes nodes [d0, d0+cnt). h1s UNscaled: per-edge dinv[s] applied here.
// Output fp16 = dinv[d]*relu(dinv[d]*sum + b1).
__global__ void __launch_bounds__(256) k_agg1(const float* __restrict__ b1, int d0, int cnt) {
    int t = blockIdx.x * blockDim.x + threadIdx.x;
    int d = (t >> 4);
    int lane = t & 15;           // channel group: 8 halves = 16B
    if (d >= cnt) return;
    d += d0;

    const uint4* __restrict__ H = (const uint4*)g_h1s;   // 16 uint4 per row
    const int* __restrict__ S = g_srcs;
    const float* __restrict__ DV = g_dinv;
    int beg = g_row[d], end = g_row[d + 1];

    float dd = __ldg(&DV[d]);
    float a[8] = {0, 0, 0, 0, 0, 0, 0, 0};
    acc8s(a, __ldg(&H[(size_t)d * 16 + lane]), dd);      // self loop: dinv[d]*h1[d]
    int e = beg;
    for (; e + 8 <= end; e += 8) {
        int   si[8]; float dv[8]; uint4 v[8];
#pragma unroll
        for (int q = 0; q < 8; q++) si[q] = __ldg(&S[e + q]);
#pragma unroll
        for (int q = 0; q < 8; q++) dv[q] = __ldg(&DV[si[q]]);
#pragma unroll
        for (int q = 0; q < 8; q++) v[q] = __ldg(&H[(size_t)si[q] * 16 + lane]);
#pragma unroll
        for (int q = 0; q < 8; q++) acc8s(a, v[q], dv[q]);
    }
    for (; e + 4 <= end; e += 4) {
        int s0 = __ldg(&S[e]),     s1 = __ldg(&S[e + 1]);
        int s2 = __ldg(&S[e + 2]), s3 = __ldg(&S[e + 3]);
        float d0v = __ldg(&DV[s0]), d1v = __ldg(&DV[s1]);
        float d2v = __ldg(&DV[s2]), d3v = __ldg(&DV[s3]);
        uint4 v0 = __ldg(&H[(size_t)s0 * 16 + lane]);
        uint4 v1 = __ldg(&H[(size_t)s1 * 16 + lane]);
        uint4 v2 = __ldg(&H[(size_t)s2 * 16 + lane]);
        uint4 v3 = __ldg(&H[(size_t)s3 * 16 + lane]);
        acc8s(a, v0, d0v); acc8s(a, v1, d1v); acc8s(a, v2, d2v); acc8s(a, v3, d3v);
    }
    for (; e < end; e++) {
        int s = __ldg(&S[e]);
        acc8s(a, __ldg(&H[(size_t)s * 16 + lane]), __ldg(&DV[s]));
    }

    float4 b0 = __ldg(&((const float4*)b1)[lane * 2]);
    float4 b4 = __ldg(&((const float4*)b1)[lane * 2 + 1]);
    float o[8];
    o[0] = fmaxf(fmaf(a[0], dd, b0.x), 0.f) * dd;
    o[1] = fmaxf(fmaf(a[1], dd, b0.y), 0.f) * dd;
    o[2] = fmaxf(fmaf(a[2], dd, b0.z), 0.f) * dd;
    o[3] = fmaxf(fmaf(a[3], dd, b0.w), 0.f) * dd;
    o[4] = fmaxf(fmaf(a[4], dd, b4.x), 0.f) * dd;
    o[5] = fmaxf(fmaf(a[5], dd, b4.y), 0.f) * dd;
    o[6] = fmaxf(fmaf(a[6], dd, b4.z), 0.f) * dd;
    o[7] = fmaxf(fmaf(a[7], dd, b4.w), 0.f) * dd;
    __half hv[8];
#pragma unroll
    for (int j = 0; j < 8; j++) hv[j] = __float2half_rn(o[j]);
    *(uint4*)(g_agg1r + (size_t)d * HID_C + lane * 8) = *(uint4*)hv;
}

// ---------------- layer-2 pull aggregation: 8 lanes per dst node (8 ch each) ----------------
__global__ void __launch_bounds__(256) k_agg2(const float* __restrict__ b2,
                                              float* __restrict__ out) {
    int t = blockIdx.x * blockDim.x + threadIdx.x;
    int d = t >> 3;
    int lane = t & 7;            // channel group: 8 halves = 16B
    if (d >= N_NODES) return;

    const uint4* __restrict__ H = (const uint4*)g_h2s;   // 8 uint4 per row
    const int* __restrict__ S = g_srcs;
    int beg = g_row[d], end = g_row[d + 1];

    float a[8] = {0, 0, 0, 0, 0, 0, 0, 0};
    acc8(a, __ldg(&H[(size_t)d * 8 + lane]));            // self loop
    int e = beg;
    for (; e + 8 <= end; e += 8) {
        int si[8]; uint4 v[8];
#pragma unroll
        for (int q = 0; q < 8; q++) si[q] = __ldg(&S[e + q]);
#pragma unroll
        for (int q = 0; q < 8; q++) v[q] = __ldg(&H[(size_t)si[q] * 8 + lane]);
#pragma unroll
        for (int q = 0; q < 8; q++) acc8(a, v[q]);
    }
    for (; e + 4 <= end; e += 4) {
        int s0 = __ldg(&S[e]),     s1 = __ldg(&S[e + 1]);
        int s2 = __ldg(&S[e + 2]), s3 = __ldg(&S[e + 3]);
        uint4 v0 = __ldg(&H[(size_t)s0 * 8 + lane]);
        uint4 v1 = __ldg(&H[(size_t)s1 * 8 + lane]);
        uint4 v2 = __ldg(&H[(size_t)s2 * 8 + lane]);
        uint4 v3 = __ldg(&H[(size_t)s3 * 8 + lane]);
        acc8(a, v0); acc8(a, v1); acc8(a, v2); acc8(a, v3);
    }
    for (; e < end; e++) {
        int s = __ldg(&S[e]);
        acc8(a, __ldg(&H[(size_t)s * 8 + lane]));
    }

    float di = g_dinv[d];
    float4 b0 = __ldg(&((const float4*)b2)[lane * 2]);
    float4 b4 = __ldg(&((const float4*)b2)[lane * 2 + 1]);
    float4 o0, o1;
    o0.x = fmaf(a[0], di, b0.x);
    o0.y = fmaf(a[1], di, b0.y);
    o0.z = fmaf(a[2], di, b0.z);
    o0.w = fmaf(a[3], di, b0.w);
    o1.x = fmaf(a[4], di, b4.x);
    o1.y = fmaf(a[5], di, b4.y);
    o1.z = fmaf(a[6], di, b4.z);
    o1.w = fmaf(a[7], di, b4.w);
    float4* op = (float4*)(out + (size_t)d * OUT_C + lane * 8);
    op[0] = o0;
    op[1] = o1;
}

// ---------------- launch ----------------
extern "C" void kernel_launch(void* const* d_in, const int* in_sizes, int n_in,
                              void* d_out, int out_size) {
    const float* x  = (const float*)d_in[0];
    const int*   ei = (const int*)  d_in[1];
    const float* W1 = (const float*)d_in[2];
    const float* b1 = (const float*)d_in[3];
    const float* W2 = (const float*)d_in[4];
    const float* b2 = (const float*)d_in[5];
    const int* src = ei;
    const int* dst = ei + N_EDGES;
    float* out = (float*)d_out;

    __half *h1sp, *h2sp, *w1tp, *w2tp, *agg1rp;
    int* cntp;
    cudaGetSymbolAddress((void**)&h1sp,   g_h1s);
    cudaGetSymbolAddress((void**)&agg1rp, g_agg1r);
    cudaGetSymbolAddress((void**)&h2sp,   g_h2s);
    cudaGetSymbolAddress((void**)&w1tp,   g_w1t);
    cudaGetSymbolAddress((void**)&w2tp,   g_w2t);
    cudaGetSymbolAddress((void**)&cntp,   g_cnt);

    // side stream + events (created once; no device memory allocated)
    static cudaStream_t s2 = [] {
        cudaStream_t s; cudaStreamCreateWithFlags(&s, cudaStreamNonBlocking); return s;
    }();
    static cudaEvent_t ev_fork = [] {
        cudaEvent_t e; cudaEventCreateWithFlags(&e, cudaEventDisableTiming); return e;
    }();
    static cudaEvent_t ev_g1 = [] {
        cudaEvent_t e; cudaEventCreateWithFlags(&e, cudaEventDisableTiming); return e;
    }();
    static cudaEvent_t ev_a1c0 = [] {
        cudaEvent_t e; cudaEventCreateWithFlags(&e, cudaEventDisableTiming); return e;
    }();
    static cudaEvent_t ev_g2c0 = [] {
        cudaEvent_t e; cudaEventCreateWithFlags(&e, cudaEventDisableTiming); return e;
    }();

    const int NB_E4 = (N_EDGES / 4 + 255) / 256;
    const int CHUNK1 = N_NODES - CHUNK0;

    // fork: branch A (s2) = weight prep + gemm1 (no dinv dependency)
    cudaEventRecord(ev_fork, 0);
    cudaStreamWaitEvent(s2, ev_fork, 0);
    k_prep_w<<<96, 256, 0, s2>>>(W1, W2);
    k_gemm_mma<HID_C, float><<<(N_NODES + 127) / 128, 256, 0, s2>>>(x, w1tp, h1sp, N_NODES, 0);
    cudaEventRecord(ev_g1, s2);

    // branch B (main): CSR build (counting sort by dst) + dinv
    cudaMemsetAsync(cntp, 0, (size_t)N_NODES * sizeof(int), 0);
    k_hist<<<NB_E4, 256>>>(dst);
    k_scan1<<<N_SCAN_BLKS, SCAN_B>>>();
    k_scan3<<<(N_NODES + 255) / 256, 256>>>();
    k_fill<<<NB_E4, 256>>>(src, dst);

    // join gemm1; then pipelined agg1 / gemm2 in two node chunks
    cudaStreamWaitEvent(0, ev_g1, 0);
    k_agg1<<<(CHUNK0 * 16 + 255) / 256, 256>>>(b1, 0, CHUNK0);
    cudaEventRecord(ev_a1c0, 0);

    // gemm2 chunk0 on s2, overlapping agg1 chunk1 on main
    cudaStreamWaitEvent(s2, ev_a1c0, 0);
    k_gemm_mma<OUT_C, __half><<<CHUNK0 / 128, 256, 0, s2>>>(agg1rp, w2tp, h2sp, CHUNK0, 0);
    cudaEventRecord(ev_g2c0, s2);

    k_agg1<<<(CHUNK1 * 16 + 255) / 256, 256>>>(b1, CHUNK0, CHUNK1);
    k_gemm_mma<OUT_C, __half><<<(CHUNK1 + 127) / 128, 256>>>(agg1rp, w2tp, h2sp, N_NODES, CHUNK0);

    // join gemm2 chunk0, then final aggregation
    cudaStreamWaitEvent(0, ev_g2c0, 0);
    k_agg2<<<(N_NODES * 8 + 255) / 256, 256>>>(b2, out);
}

// round 14
// speedup vs baseline: 1.0401x; 1.0401x over previous
#include <cuda_runtime.h>
#include <cuda_fp16.h>
#include <mma.h>
#include <cstddef>

#define N_NODES 100000
#define N_EDGES 1600000
#define IN_C  128
#define HID_C 128
#define OUT_C 64

#define SCAN_B 512
#define N_SCAN_BLKS ((N_NODES + SCAN_B - 1) / SCAN_B)   // 196

// ---------------- scratch (module-static; no allocations) ----------------
__device__ int    g_cnt   [N_NODES];
__device__ int    g_row   [N_NODES + 1];
__device__ int    g_bsum  [N_SCAN_BLKS];
__device__ int    g_rank  [N_EDGES];                     // edge rank within its dst group
__device__ int    g_srcs  [N_EDGES];                     // src ids sorted by dst
__device__ float  g_dinv  [N_NODES];
__device__ __half g_w1t   [(size_t)HID_C * IN_C];        // W1^T fp16: [n][k]
__device__ __half g_w2t   [(size_t)OUT_C * HID_C];       // W2^T fp16: [n][k]
__device__ __half g_h1s   [(size_t)N_NODES * HID_C];     // fp16: (x @ W1)[n]  (UNscaled)
__device__ __half g_agg1r [(size_t)N_NODES * HID_C];     // fp16: dinv[n]*relu(layer1[n])
__device__ __half g_h2s   [(size_t)N_NODES * OUT_C];     // fp16: dinv[n]*(relu1[n] @ W2)

// ---------------- GEMM-branch init: weight transpose/convert ----------------
__global__ void k_prep_w(const float* __restrict__ W1, const float* __restrict__ W2) {
    int i = blockIdx.x * blockDim.x + threadIdx.x;
    int stride = gridDim.x * blockDim.x;
    for (int j = i; j < HID_C * IN_C; j += stride) {     // Wt1[n][k] = W1[k][n]
        int n = j / IN_C, k = j % IN_C;
        g_w1t[j] = __float2half_rn(W1[(size_t)k * HID_C + n]);
    }
    for (int j = i; j < OUT_C * HID_C; j += stride) {    // Wt2[n][k] = W2[k][n]
        int n = j / HID_C, k = j % HID_C;
        g_w2t[j] = __float2half_rn(W2[(size_t)k * OUT_C + n]);
    }
}

// 4 edges per thread; record per-edge rank within its dst group (atomic return value)
__global__ void k_hist(const int* __restrict__ dst) {
    int i = blockIdx.x * blockDim.x + threadIdx.x;
    if (i < N_EDGES / 4) {
        int4 d = __ldg(&((const int4*)dst)[i]);
        int4 r;
        r.x = atomicAdd(&g_cnt[d.x], 1);
        r.y = atomicAdd(&g_cnt[d.y], 1);
        r.z = atomicAdd(&g_cnt[d.z], 1);
        r.w = atomicAdd(&g_cnt[d.w], 1);
        ((int4*)g_rank)[i] = r;
    }
}

// per-block inclusive scan of 512 counts; also computes dinv = rsqrt(cnt+1)
__global__ void k_scan1() {
    __shared__ int sh[SCAN_B];
    int i = blockIdx.x * SCAN_B + threadIdx.x;
    int v = (i < N_NODES) ? g_cnt[i] : 0;
    if (i < N_NODES) g_dinv[i] = rsqrtf((float)(v + 1));   // +1 self loop
    sh[threadIdx.x] = v;
    __syncthreads();
#pragma unroll
    for (int off = 1; off < SCAN_B; off <<= 1) {
        int t = (threadIdx.x >= off) ? sh[threadIdx.x - off] : 0;
        __syncthreads();
        sh[threadIdx.x] += t;
        __syncthreads();
    }
    if (i < N_NODES) g_row[i] = sh[threadIdx.x] - v;       // exclusive within block
    if (threadIdx.x == SCAN_B - 1) g_bsum[blockIdx.x] = sh[SCAN_B - 1];
}

// each block redundantly scans the 196 block sums, then applies offsets
__global__ void k_scan3() {
    __shared__ int bo[256];
    int t = threadIdx.x;
    int v = (t < N_SCAN_BLKS) ? g_bsum[t] : 0;
    bo[t] = v;
    __syncthreads();
#pragma unroll
    for (int off = 1; off < 256; off <<= 1) {
        int u = (t >= off) ? bo[t - off] : 0;
        __syncthreads();
        bo[t] += u;
        __syncthreads();
    }
    // exclusive offset for block b = bo[b] - bsum[b]
    int i = blockIdx.x * blockDim.x + t;
    if (i < N_NODES) {
        g_row[i] = g_row[i] + bo[i >> 9] - g_bsum[i >> 9];
    }
    if (blockIdx.x == 0 && t == 0) g_row[N_NODES] = N_EDGES;
}

// atomic-free fill: srcs[row[dst] + rank] = src
__global__ void k_fill(const int* __restrict__ src, const int* __restrict__ dst) {
    int i = blockIdx.x * blockDim.x + threadIdx.x;
    if (i < N_EDGES / 4) {
        int4 d = __ldg(&((const int4*)dst)[i]);
        int4 s = __ldg(&((const int4*)src)[i]);
        int4 r = __ldg(&((const int4*)g_rank)[i]);
        g_srcs[g_row[d.x] + r.x] = s.x;
        g_srcs[g_row[d.y] + r.y] = s.y;
        g_srcs[g_row[d.z] + r.z] = s.z;
        g_srcs[g_row[d.w] + r.w] = s.w;
    }
}

// ---------------- tensor-core GEMM: C[M,NC] = half( A[M,128] @ Wt^T ) ----------------
// A (fp32 or fp16) row-major stride 128, Wt fp16 [NC][128], C fp16 row-major stride NC.
template<int NC, typename TA>
__global__ void __launch_bounds__(256) k_gemm_mma(const TA* __restrict__ A,
                                                  const __half* __restrict__ Wt,
                                                  __half* __restrict__ C, int M) {
    using namespace nvcuda;
    constexpr int KC = 64, ST = KC + 16;   // smem stride (halves), 32B-aligned rows
    constexpr int NFR = NC / 32;           // n-frags per warp: 128->4, 64->2

    __shared__ __half As[128 * ST];
    __shared__ __half Bs[NC * ST];

    const int tid    = threadIdx.x;
    const int wid    = tid >> 5;
    const int lane   = tid & 31;
    const int warp_m = wid & 3;            // 4 warp-rows x 32 rows
    const int warp_n = wid >> 2;           // 2 warp-cols x NC/2 cols
    const int row_blk = blockIdx.x * 128;

    wmma::fragment<wmma::accumulator, 16, 16, 16, float> cf[2][NFR];
#pragma unroll
    for (int i = 0; i < 2; i++)
#pragma unroll
        for (int j = 0; j < NFR; j++) wmma::fill_fragment(cf[i][j], 0.f);

    for (int kc = 0; kc < 128; kc += KC) {
        // A chunk: 128 rows x 64 elems as fp16. 2 thr/row (32 elems each).
        {
            int r = tid >> 1;
            int hh = tid & 1;
            int grow = row_blk + r;
            __half* sp = As + r * ST + hh * 32;
            if (sizeof(TA) == 4) {         // fp32 input: convert
                const float4* gp = (const float4*)((const float*)A + (size_t)grow * 128 + kc + hh * 32);
#pragma unroll
                for (int j = 0; j < 8; j++) {
                    float4 v = (grow < M) ? __ldg(&gp[j]) : make_float4(0.f, 0.f, 0.f, 0.f);
                    ((__half2*)(sp + j * 4))[0] = __floats2half2_rn(v.x, v.y);
                    ((__half2*)(sp + j * 4))[1] = __floats2half2_rn(v.z, v.w);
                }
            } else {                       // fp16 input: pure uint4 copy
                const uint4* gp = (const uint4*)((const __half*)A + (size_t)grow * 128 + kc + hh * 32);
#pragma unroll
                for (int j = 0; j < 4; j++) {
                    uint4 v = (grow < M) ? __ldg(&gp[j]) : make_uint4(0, 0, 0, 0);
                    *(uint4*)(sp + j * 8) = v;
                }
            }
        }
        // B chunk: NC rows x 64 halves (uint4 copies)
        {
#pragma unroll
            for (int i = 0; i < (NC * 8) / 256; i++) {
                int u = tid + i * 256;
                int n = u >> 3, k8 = u & 7;
                uint4 v = *(const uint4*)(Wt + (size_t)n * 128 + kc + k8 * 8);
                *(uint4*)(Bs + n * ST + k8 * 8) = v;
            }
        }
        __syncthreads();

#pragma unroll
        for (int kf = 0; kf < KC / 16; kf++) {
            wmma::fragment<wmma::matrix_a, 16, 16, 16, __half, wmma::row_major> af[2];
            wmma::load_matrix_sync(af[0], As + (warp_m * 32 +  0) * ST + kf * 16, ST);
            wmma::load_matrix_sync(af[1], As + (warp_m * 32 + 16) * ST + kf * 16, ST);
#pragma unroll
            for (int nf = 0; nf < NFR; nf++) {
                wmma::fragment<wmma::matrix_b, 16, 16, 16, __half, wmma::col_major> bf;
                wmma::load_matrix_sync(bf, Bs + (warp_n * (NC / 2) + nf * 16) * ST + kf * 16, ST);
                wmma::mma_sync(cf[0][nf], af[0], bf, cf[0][nf]);
                wmma::mma_sync(cf[1][nf], af[1], bf, cf[1][nf]);
            }
        }
        __syncthreads();   // protects As/Bs before next chunk / staging reuse
    }

    // epilogue: stage fp32 frag -> convert fp16 -> gmem (per-warp disjoint staging in As)
    float* stage = (float*)As + wid * 256;
#pragma unroll
    for (int mf = 0; mf < 2; mf++) {
        int row0 = row_blk + warp_m * 32 + mf * 16;
        if (row0 + 16 > M) continue;          // M is a multiple of 16
#pragma unroll
        for (int nf = 0; nf < NFR; nf++) {
            wmma::store_matrix_sync(stage, cf[mf][nf], 16, wmma::mem_row_major);
            __syncwarp();
            int r = lane >> 1, c = (lane & 1) * 8;
            const float* sp = stage + r * 16 + c;
            __half hv[8];
#pragma unroll
            for (int j = 0; j < 8; j++) hv[j] = __float2half_rn(sp[j]);
            int col0 = warp_n * (NC / 2) + nf * 16 + c;
            *(uint4*)(C + (size_t)(row0 + r) * NC + col0) = *(uint4*)hv;
            __syncwarp();
        }
    }
}

// accumulate 8 fp16 channels (one uint4) scaled by s into fp32 accumulator
__device__ __forceinline__ void acc8s(float* a, uint4 u, float s) {
    const __half2* h = (const __half2*)&u;
#pragma unroll
    for (int i = 0; i < 4; i++) {
        float2 f = __half22float2(h[i]);
        a[2 * i]     = fmaf(f.x, s, a[2 * i]);
        a[2 * i + 1] = fmaf(f.y, s, a[2 * i + 1]);
    }
}

// accumulate 8 fp16 channels (one uint4) into fp32 accumulator
__device__ __forceinline__ void acc8(float* a, uint4 u) {
    const __half2* h = (const __half2*)&u;
#pragma unroll
    for (int i = 0; i < 4; i++) {
        float2 f = __half22float2(h[i]);
        a[2 * i]     += f.x;
        a[2 * i + 1] += f.y;
    }
}

// ---------------- layer-1 pull aggregation: 16 lanes per dst node (8 ch each) ----------------
// h1s UNscaled: per-edge dinv[s] applied here. Output fp16 = dinv[d]*relu(dinv[d]*sum + b1).
__global__ void __launch_bounds__(256) k_agg1(const float* __restrict__ b1) {
    int t = blockIdx.x * blockDim.x + threadIdx.x;
    int d = t >> 4;
    int lane = t & 15;           // channel group: 8 halves = 16B
    if (d >= N_NODES) return;

    const uint4* __restrict__ H = (const uint4*)g_h1s;   // 16 uint4 per row
    const int* __restrict__ S = g_srcs;
    const float* __restrict__ DV = g_dinv;
    int beg = g_row[d], end = g_row[d + 1];

    float dd = __ldg(&DV[d]);
    float a[8] = {0, 0, 0, 0, 0, 0, 0, 0};
    acc8s(a, __ldg(&H[(size_t)d * 16 + lane]), dd);      // self loop: dinv[d]*h1[d]
    int e = beg;
    for (; e + 8 <= end; e += 8) {
        int   si[8]; float dv[8]; uint4 v[8];
#pragma unroll
        for (int q = 0; q < 8; q++) si[q] = __ldg(&S[e + q]);
#pragma unroll
        for (int q = 0; q < 8; q++) dv[q] = __ldg(&DV[si[q]]);
#pragma unroll
        for (int q = 0; q < 8; q++) v[q] = __ldg(&H[(size_t)si[q] * 16 + lane]);
#pragma unroll
        for (int q = 0; q < 8; q++) acc8s(a, v[q], dv[q]);
    }
    for (; e + 4 <= end; e += 4) {
        int s0 = __ldg(&S[e]),     s1 = __ldg(&S[e + 1]);
        int s2 = __ldg(&S[e + 2]), s3 = __ldg(&S[e + 3]);
        float d0v = __ldg(&DV[s0]), d1v = __ldg(&DV[s1]);
        float d2v = __ldg(&DV[s2]), d3v = __ldg(&DV[s3]);
        uint4 v0 = __ldg(&H[(size_t)s0 * 16 + lane]);
        uint4 v1 = __ldg(&H[(size_t)s1 * 16 + lane]);
        uint4 v2 = __ldg(&H[(size_t)s2 * 16 + lane]);
        uint4 v3 = __ldg(&H[(size_t)s3 * 16 + lane]);
        acc8s(a, v0, d0v); acc8s(a, v1, d1v); acc8s(a, v2, d2v); acc8s(a, v3, d3v);
    }
    for (; e < end; e++) {
        int s = __ldg(&S[e]);
        acc8s(a, __ldg(&H[(size_t)s * 16 + lane]), __ldg(&DV[s]));
    }

    float4 b0 = __ldg(&((const float4*)b1)[lane * 2]);
    float4 b4 = __ldg(&((const float4*)b1)[lane * 2 + 1]);
    float o[8];
    o[0] = fmaxf(fmaf(a[0], dd, b0.x), 0.f) * dd;
    o[1] = fmaxf(fmaf(a[1], dd, b0.y), 0.f) * dd;
    o[2] = fmaxf(fmaf(a[2], dd, b0.z), 0.f) * dd;
    o[3] = fmaxf(fmaf(a[3], dd, b0.w), 0.f) * dd;
    o[4] = fmaxf(fmaf(a[4], dd, b4.x), 0.f) * dd;
    o[5] = fmaxf(fmaf(a[5], dd, b4.y), 0.f) * dd;
    o[6] = fmaxf(fmaf(a[6], dd, b4.z), 0.f) * dd;
    o[7] = fmaxf(fmaf(a[7], dd, b4.w), 0.f) * dd;
    __half hv[8];
#pragma unroll
    for (int j = 0; j < 8; j++) hv[j] = __float2half_rn(o[j]);
    *(uint4*)(g_agg1r + (size_t)d * HID_C + lane * 8) = *(uint4*)hv;
}

// ---------------- layer-2 pull aggregation: 8 lanes per dst node (8 ch each) ----------------
__global__ void __launch_bounds__(256) k_agg2(const float* __restrict__ b2,
                                              float* __restrict__ out) {
    int t = blockIdx.x * blockDim.x + threadIdx.x;
    int d = t >> 3;
    int lane = t & 7;            // channel group: 8 halves = 16B
    if (d >= N_NODES) return;

    const uint4* __restrict__ H = (const uint4*)g_h2s;   // 8 uint4 per row
    const int* __restrict__ S = g_srcs;
    int beg = g_row[d], end = g_row[d + 1];

    float a[8] = {0, 0, 0, 0, 0, 0, 0, 0};
    acc8(a, __ldg(&H[(size_t)d * 8 + lane]));            // self loop
    int e = beg;
    for (; e + 8 <= end; e += 8) {
        int si[8]; uint4 v[8];
#pragma unroll
        for (int q = 0; q < 8; q++) si[q] = __ldg(&S[e + q]);
#pragma unroll
        for (int q = 0; q < 8; q++) v[q] = __ldg(&H[(size_t)si[q] * 8 + lane]);
#pragma unroll
        for (int q = 0; q < 8; q++) acc8(a, v[q]);
    }
    for (; e + 4 <= end; e += 4) {
        int s0 = __ldg(&S[e]),     s1 = __ldg(&S[e + 1]);
        int s2 = __ldg(&S[e + 2]), s3 = __ldg(&S[e + 3]);
        uint4 v0 = __ldg(&H[(size_t)s0 * 8 + lane]);
        uint4 v1 = __ldg(&H[(size_t)s1 * 8 + lane]);
        uint4 v2 = __ldg(&H[(size_t)s2 * 8 + lane]);
        uint4 v3 = __ldg(&H[(size_t)s3 * 8 + lane]);
        acc8(a, v0); acc8(a, v1); acc8(a, v2); acc8(a, v3);
    }
    for (; e < end; e++) {
        int s = __ldg(&S[e]);
        acc8(a, __ldg(&H[(size_t)s * 8 + lane]));
    }

    float di = g_dinv[d];
    float4 b0 = __ldg(&((const float4*)b2)[lane * 2]);
    float4 b4 = __ldg(&((const float4*)b2)[lane * 2 + 1]);
    float4 o0, o1;
    o0.x = fmaf(a[0], di, b0.x);
    o0.y = fmaf(a[1], di, b0.y);
    o0.z = fmaf(a[2], di, b0.z);
    o0.w = fmaf(a[3], di, b0.w);
    o1.x = fmaf(a[4], di, b4.x);
    o1.y = fmaf(a[5], di, b4.y);
    o1.z = fmaf(a[6], di, b4.z);
    o1.w = fmaf(a[7], di, b4.w);
    float4* op = (float4*)(out + (size_t)d * OUT_C + lane * 8);
    op[0] = o0;
    op[1] = o1;
}

// ---------------- launch ----------------
extern "C" void kernel_launch(void* const* d_in, const int* in_sizes, int n_in,
                              void* d_out, int out_size) {
    const float* x  = (const float*)d_in[0];
    const int*   ei = (const int*)  d_in[1];
    const float* W1 = (const float*)d_in[2];
    const float* b1 = (const float*)d_in[3];
    const float* W2 = (const float*)d_in[4];
    const float* b2 = (const float*)d_in[5];
    const int* src = ei;
    const int* dst = ei + N_EDGES;
    float* out = (float*)d_out;

    __half *h1sp, *h2sp, *w1tp, *w2tp, *agg1rp;
    int* cntp;
    cudaGetSymbolAddress((void**)&h1sp,   g_h1s);
    cudaGetSymbolAddress((void**)&agg1rp, g_agg1r);
    cudaGetSymbolAddress((void**)&h2sp,   g_h2s);
    cudaGetSymbolAddress((void**)&w1tp,   g_w1t);
    cudaGetSymbolAddress((void**)&w2tp,   g_w2t);
    cudaGetSymbolAddress((void**)&cntp,   g_cnt);

    // side stream + fork/join events (created once; no device memory allocated)
    static cudaStream_t s2 = [] {
        cudaStream_t s; cudaStreamCreateWithFlags(&s, cudaStreamNonBlocking); return s;
    }();
    static cudaEvent_t ev_fork = [] {
        cudaEvent_t e; cudaEventCreateWithFlags(&e, cudaEventDisableTiming); return e;
    }();
    static cudaEvent_t ev_join = [] {
        cudaEvent_t e; cudaEventCreateWithFlags(&e, cudaEventDisableTiming); return e;
    }();

    const int NB_E4 = (N_EDGES / 4 + 255) / 256;

    // fork: branch A (s2) = weight prep + gemm1 (no dinv dependency)
    cudaEventRecord(ev_fork, 0);
    cudaStreamWaitEvent(s2, ev_fork, 0);
    k_prep_w<<<96, 256, 0, s2>>>(W1, W2);
    k_gemm_mma<HID_C, float><<<(N_NODES + 127) / 128, 256, 0, s2>>>(x, w1tp, h1sp, N_NODES);
    cudaEventRecord(ev_join, s2);

    // branch B (main): CSR build (counting sort by dst) + dinv
    cudaMemsetAsync(cntp, 0, (size_t)N_NODES * sizeof(int), 0);
    k_hist<<<NB_E4, 256>>>(dst);
    k_scan1<<<N_SCAN_BLKS, SCAN_B>>>();
    k_scan3<<<(N_NODES + 255) / 256, 256>>>();
    k_fill<<<NB_E4, 256>>>(src, dst);

    // join: agg1 needs both branches
    cudaStreamWaitEvent(0, ev_join, 0);
    k_agg1<<<(N_NODES * 16 + 255) / 256, 256>>>(b1);

    // layer 2: gemm2 reads pre-scaled fp16 agg1r (pure copy loader)
    k_gemm_mma<OUT_C, __half><<<(N_NODES + 127) / 128, 256>>>(agg1rp, w2tp, h2sp, N_NODES);
    k_agg2<<<(N_NODES * 8 + 255) / 256, 256>>>(b2, out);
}